// round 7
// baseline (speedup 1.0000x reference)
#include <cuda_runtime.h>
#include <cuda_bf16.h>
#include <cstdint>
#include <math.h>

#define BB 16384
#define DD 4096
#define HH 128

// ---------------- scratch ----------------
__device__ __nv_bfloat16 g_xb[(size_t)BB * DD];     // visible sample (in-place chain)
__device__ __nv_bfloat16 g_Wx[2][(size_t)DD * HH];  // W splits, [d][h] (x-phase B)
__device__ __nv_bfloat16 g_Wh[2][(size_t)DD * HH];  // W splits, [h][d] (h-phase B)
__device__ double g_acc[4];

// ---------------- threefry2x32 (JAX-exact, verified R1-R5) ----------------
__host__ __device__ __forceinline__ uint32_t rotl32(uint32_t v, int s) {
  return (v << s) | (v >> (32 - s));
}
__host__ __device__ __forceinline__ void tf2x32(uint32_t k0, uint32_t k1,
                                                uint32_t x0, uint32_t x1,
                                                uint32_t &o0, uint32_t &o1) {
  uint32_t ks2 = k0 ^ k1 ^ 0x1BD11BDAu;
  x0 += k0; x1 += k1;
#define TF_R(r) { x0 += x1; x1 = rotl32(x1, r); x1 ^= x0; }
  TF_R(13) TF_R(15) TF_R(26) TF_R(6)   x0 += k1;  x1 += ks2 + 1u;
  TF_R(17) TF_R(29) TF_R(16) TF_R(24)  x0 += ks2; x1 += k0 + 2u;
  TF_R(13) TF_R(15) TF_R(26) TF_R(6)   x0 += k0;  x1 += k1 + 3u;
  TF_R(17) TF_R(29) TF_R(16) TF_R(24)  x0 += k1;  x1 += ks2 + 4u;
  TF_R(13) TF_R(15) TF_R(26) TF_R(6)   x0 += ks2; x1 += k0 + 5u;
#undef TF_R
  o0 = x0; o1 = x1;
}
__device__ __forceinline__ float jax_uniform01(uint32_t k0, uint32_t k1, uint32_t idx) {
  uint32_t a, b;
  tf2x32(k0, k1, 0u, idx, a, b);
  uint32_t bits = a ^ b;
  return __uint_as_float((bits >> 9) | 0x3F800000u) - 1.0f;
}
__device__ __forceinline__ float fast_sigmoid(float x) {
  float e, r;
  asm("ex2.approx.f32 %0, %1;" : "=f"(e) : "f"(-1.4426950408889634f * x));
  asm("rcp.approx.f32 %0, %1;" : "=f"(r) : "f"(1.0f + e));
  return r;
}
__device__ __forceinline__ float softplusf_(float x) {
  return fmaxf(x, 0.0f) + log1pf(expf(-fabsf(x)));
}

// ---------------- PTX helpers (baseline sm_100-safe) ----------------
__device__ __forceinline__ uint32_t smem_u32(const void *p) {
  uint32_t a;
  asm("{ .reg .u64 t; cvta.to.shared.u64 t, %1; cvt.u32.u64 %0, t; }"
      : "=r"(a) : "l"(p));
  return a;
}
__device__ __forceinline__ void ldsm4(uint32_t *r, uint32_t a) {
  asm volatile("ldmatrix.sync.aligned.m8n8.x4.shared.b16 {%0,%1,%2,%3}, [%4];"
               : "=r"(r[0]), "=r"(r[1]), "=r"(r[2]), "=r"(r[3]) : "r"(a));
}
__device__ __forceinline__ void mma_bf16(float *c, const uint32_t *a,
                                         uint32_t b0, uint32_t b1) {
  asm volatile(
      "mma.sync.aligned.m16n8k16.row.col.f32.bf16.bf16.f32 "
      "{%0,%1,%2,%3}, {%4,%5,%6,%7}, {%8,%9}, {%0,%1,%2,%3};"
      : "+f"(c[0]), "+f"(c[1]), "+f"(c[2]), "+f"(c[3])
      : "r"(a[0]), "r"(a[1]), "r"(a[2]), "r"(a[3]), "r"(b0), "r"(b1));
}
__device__ __forceinline__ uint32_t sw128(uint32_t o) {
  return o ^ ((o >> 3) & 0x70);
}

// ---------------- smem layout (per CTA, 2 CTAs/SM) ----------------
// [0, 16384)      h buffer: 2 k-chunks x [64 rows x 128B] (SW128 tiles)
// [16384, 81920)  B pipeline: 2 stages x (2 splits x 16KB)
// [81920, 98816)  h-phase A pipeline (2 x 8KB)  UNION  x-phase staging (64x264B)
static constexpr int SM_H = 0;
static constexpr int SM_B = 16384;
static constexpr int SM_X = 81920;
static constexpr int SMEM_BYTES = 98816;

// load [ROWS x 64 bf16] tile, 128B rows, SW128-swizzled, via cp.async
template <int LD, int ROWS>
__device__ __forceinline__ void load_tile(uint32_t sdst, const __nv_bfloat16 *g,
                                          int row0, int kt) {
  int t = threadIdx.x;
#pragma unroll
  for (int i = 0; i < ROWS / 32; i++) {
    int idx = t + 256 * i;
    int r = idx >> 3, c = idx & 7;
    uint32_t sw = sw128((uint32_t)(r * 128 + c * 16));
    const void *ga = (const void *)(g + (size_t)(row0 + r) * LD + kt + c * 8);
    asm volatile("cp.async.cg.shared.global [%0], [%1], 16;"
                 :: "r"(sdst + sw), "l"(ga));
  }
}

// =============================================================
// Fused CD-4 chain. Each CTA owns 64 batch rows and runs:
//   5x h-GEMM (M64 N128 K4096, 2 splits) + 4x x-GEMM (M64 N4096 K128, 2 splits)
// with threefry sampling epilogues. h lives entirely in smem.
// =============================================================
__global__ void __launch_bounds__(256, 2)
fused_cd_kernel(const float *__restrict__ bx_, const float *__restrict__ bh_) {
  extern __shared__ char smem[];
  const uint32_t sb = smem_u32(smem);
  const int t = threadIdx.x, wid = t >> 5, l = t & 31;
  const int wm = wid & 1, wn = wid >> 1;
  const int m0 = blockIdx.x * 64;
  const int q = l >> 2, tq = l & 3;

  uint32_t offA[2], offB[2];
#pragma unroll
  for (int i = 0; i < 2; i++)
    offA[i] = (uint32_t)((wm * 32 + i * 16 + (l & 15)) * 128 + ((l >> 4) & 1) * 16);
#pragma unroll
  for (int jb = 0; jb < 2; jb++)
    offB[jb] = (uint32_t)((wn * 32 + jb * 16 + (l & 7) + ((l >> 4) & 1) * 8) * 128 +
                          ((l >> 3) & 1) * 16);

  float2 bias2h[4];
#pragma unroll
  for (int j = 0; j < 4; j++)
    bias2h[j] = *(const float2 *)&bh_[wn * 32 + j * 8 + 2 * tq];

  double sp0 = 0.0, sp1 = 0.0, spb = 0.0;
  const __nv_bfloat16 onev = __float2bfloat16(1.0f);
  const __nv_bfloat16 zerov = __float2bfloat16(0.0f);

  float acc[2][4][4];
  auto zacc = [&] {
#pragma unroll
    for (int i = 0; i < 2; i++)
#pragma unroll
      for (int j = 0; j < 4; j++)
#pragma unroll
        for (int v = 0; v < 4; v++) acc[i][j][v] = 0.0f;
  };

  auto issue_h = [&](int c) {
    int s = c & 1, kt = c * 64;
    load_tile<DD, 64>(sb + SM_X + s * 8192, g_xb, m0, kt);
    load_tile<DD, 128>(sb + SM_B + s * 32768, g_Wh[0], 0, kt);
    load_tile<DD, 128>(sb + SM_B + s * 32768 + 16384, g_Wh[1], 0, kt);
    asm volatile("cp.async.commit_group;" ::: "memory");
  };
  auto issue_x = [&](int c) {
    int s = c & 1, nt = c >> 1, kt = (c & 1) * 64;
    load_tile<HH, 128>(sb + SM_B + s * 32768, g_Wx[0], nt * 128, kt);
    load_tile<HH, 128>(sb + SM_B + s * 32768 + 16384, g_Wx[1], nt * 128, kt);
    asm volatile("cp.async.commit_group;" ::: "memory");
  };
  auto do_chunk = [&](uint32_t abase, uint32_t bbase) {
#pragma unroll
    for (int kk = 0; kk < 4; kk++) {
      uint32_t a[2][4];
#pragma unroll
      for (int i = 0; i < 2; i++)
        ldsm4(a[i], abase + sw128(offA[i] + kk * 32));
#pragma unroll
      for (int p = 0; p < 2; p++) {
        uint32_t bb = bbase + 16384u * p;
#pragma unroll
        for (int jb = 0; jb < 2; jb++) {
          uint32_t b[4];
          ldsm4(b, bb + sw128(offB[jb] + kk * 32));
#pragma unroll
          for (int i = 0; i < 2; i++) {
            mma_bf16(acc[i][jb * 2 + 0], a[i], b[0], b[1]);
            mma_bf16(acc[i][jb * 2 + 1], a[i], b[2], b[3]);
          }
        }
      }
    }
  };

  issue_h(0); issue_h(1);

#pragma unroll 1
  for (int step = 0; step <= 4; step++) {
    uint32_t hk0, hk1, xk0, xk1;
    tf2x32(0u, 42u, 0u, (uint32_t)(2 * step), hk0, hk1);
    tf2x32(0u, 42u, 0u, (uint32_t)(2 * step + 1), xk0, xk1);

    // ---------------- h phase: M64 N128 K4096 ----------------
    zacc();
#pragma unroll 1
    for (int c = 0; c < 64; c++) {
      if (c + 1 < 64) asm volatile("cp.async.wait_group 1;" ::: "memory");
      else            asm volatile("cp.async.wait_group 0;" ::: "memory");
      __syncthreads();
      do_chunk(sb + SM_X + (uint32_t)(c & 1) * 8192,
               sb + SM_B + (uint32_t)(c & 1) * 32768);
      __syncthreads();
      if (c + 2 < 64) issue_h(c + 2);
    }
    if (step < 4) { issue_x(0); issue_x(1); }  // overlap B loads with epilogue

    // h epilogue: softplus slots and/or sample into smem h buffer
#pragma unroll
    for (int i = 0; i < 2; i++) {
#pragma unroll
      for (int j = 0; j < 4; j++) {
        int c_loc = wn * 32 + j * 8 + 2 * tq;
#pragma unroll
        for (int h = 0; h < 2; h++) {
          int row = wm * 32 + i * 16 + q + h * 8;
          float l0 = acc[i][j][2 * h + 0] + bias2h[j].x;
          float l1 = acc[i][j][2 * h + 1] + bias2h[j].y;
          if (step == 0) sp0 += (double)softplusf_(l0) + (double)softplusf_(l1);
          if (step == 4) sp1 += (double)softplusf_(l0) + (double)softplusf_(l1);
          if (step < 4) {
            float p0 = fast_sigmoid(l0), p1 = fast_sigmoid(l1);
            uint32_t idx0 = (uint32_t)(m0 + row) * (uint32_t)HH + (uint32_t)c_loc;
            float u0 = jax_uniform01(hk0, hk1, idx0);
            float u1 = jax_uniform01(hk0, hk1, idx0 + 1u);
            __nv_bfloat162 v;
            v.x = (u0 < p0) ? onev : zerov;
            v.y = (u1 < p1) ? onev : zerov;
            uint32_t off = (uint32_t)(row * 128 + (c_loc & 63) * 2);
            *(__nv_bfloat162 *)(smem + SM_H + (c_loc >> 6) * 8192 + sw128(off)) = v;
          }
        }
      }
    }
    __syncthreads();  // h buffer visible to all warps
    if (step == 4) break;

    // ---------------- x phase: 32 tiles of M64 N128 K128 ----------------
    zacc();
#pragma unroll 1
    for (int c = 0; c < 64; c++) {
      if (c + 1 < 64) asm volatile("cp.async.wait_group 1;" ::: "memory");
      else            asm volatile("cp.async.wait_group 0;" ::: "memory");
      __syncthreads();
      do_chunk(sb + SM_H + (uint32_t)(c & 1) * 8192,
               sb + SM_B + (uint32_t)(c & 1) * 32768);
      __syncthreads();
      if (c + 2 < 64) issue_x(c + 2);  // loads overlap the epilogue below
      if (c & 1) {
        int n0 = (c >> 1) * 128;
        float2 bias2[4];
#pragma unroll
        for (int j = 0; j < 4; j++)
          bias2[j] = *(const float2 *)&bx_[n0 + wn * 32 + j * 8 + 2 * tq];
#pragma unroll
        for (int i = 0; i < 2; i++) {
#pragma unroll
          for (int j = 0; j < 4; j++) {
            int c_loc = wn * 32 + j * 8 + 2 * tq;
#pragma unroll
            for (int h = 0; h < 2; h++) {
              int row = wm * 32 + i * 16 + q + h * 8;
              float l0 = acc[i][j][2 * h + 0] + bias2[j].x;
              float l1 = acc[i][j][2 * h + 1] + bias2[j].y;
              float p0 = fast_sigmoid(l0), p1 = fast_sigmoid(l1);
              uint32_t idx0 =
                  (uint32_t)(m0 + row) * (uint32_t)DD + (uint32_t)(n0 + c_loc);
              float u0 = jax_uniform01(xk0, xk1, idx0);
              float u1 = jax_uniform01(xk0, xk1, idx0 + 1u);
              bool s0 = (u0 < p0), s1 = (u1 < p1);
              if (step == 3) {  // x_rec . bx term
                if (s0) spb += (double)bias2[j].x;
                if (s1) spb += (double)bias2[j].y;
              }
              __nv_bfloat162 v;
              v.x = s0 ? onev : zerov;
              v.y = s1 ? onev : zerov;
              *(__nv_bfloat162 *)(smem + SM_X + row * 264 + c_loc * 2) = v;
            }
          }
        }
        __syncthreads();
#pragma unroll
        for (int i2 = 0; i2 < 8; i2++) {
          int idx = t + 256 * i2;
          int rr = idx >> 5, c8 = idx & 31;
          uint64_t v = *(const uint64_t *)(smem + SM_X + rr * 264 + c8 * 8);
          *(uint64_t *)((char *)g_xb + (size_t)(m0 + rr) * (DD * 2) +
                        (size_t)n0 * 2 + c8 * 8) = v;
        }
        __syncthreads();
        zacc();
      }
    }
    issue_h(0); issue_h(1);  // prologue for next h phase (reads rows just stored)
  }

  // ---------------- reductions ----------------
#pragma unroll
  for (int o = 16; o > 0; o >>= 1) {
    sp0 += __shfl_down_sync(0xffffffffu, sp0, o);
    sp1 += __shfl_down_sync(0xffffffffu, sp1, o);
    spb += __shfl_down_sync(0xffffffffu, spb, o);
  }
  if (l == 0) {
    atomicAdd(&g_acc[0], sp0);
    atomicAdd(&g_acc[1], sp1);
    atomicAdd(&g_acc[3], spb);
  }
}

// ---------------- prep (conv fuses x.bx accumulation) ----------------
__global__ void conv_kernel(const float *__restrict__ x,
                            const float *__restrict__ bx) {
  size_t n = (size_t)BB * DD / 4;
  double s = 0.0;
  for (size_t i = (size_t)blockIdx.x * blockDim.x + threadIdx.x; i < n;
       i += (size_t)gridDim.x * blockDim.x) {
    float4 v = ((const float4 *)x)[i];
    ushort4 o;
    o.x = __bfloat16_as_ushort(__float2bfloat16(v.x));
    o.y = __bfloat16_as_ushort(__float2bfloat16(v.y));
    o.z = __bfloat16_as_ushort(__float2bfloat16(v.z));
    o.w = __bfloat16_as_ushort(__float2bfloat16(v.w));
    ((ushort4 *)g_xb)[i] = o;
    uint32_t d = (uint32_t)((i * 4) & (DD - 1));
    const float4 b4 = *(const float4 *)&bx[d];
    s += (double)(v.x * b4.x + v.y * b4.y) + (double)(v.z * b4.z + v.w * b4.w);
  }
#pragma unroll
  for (int off = 16; off > 0; off >>= 1)
    s += __shfl_down_sync(0xffffffffu, s, off);
  if ((threadIdx.x & 31) == 0) atomicAdd(&g_acc[2], s);
}

__global__ void wsplit_kernel(const float *__restrict__ W) {
  int n = DD * HH;
  for (int i = blockIdx.x * blockDim.x + threadIdx.x; i < n;
       i += gridDim.x * blockDim.x) {
    float w = W[i];
    __nv_bfloat16 b0 = __float2bfloat16(w);
    float r1 = w - __bfloat162float(b0);
    __nv_bfloat16 b1 = __float2bfloat16(r1);
    g_Wx[0][i] = b0; g_Wx[1][i] = b1;
    int d = i >> 7, h = i & 127;
    int j = h * DD + d;
    g_Wh[0][j] = b0; g_Wh[1][j] = b1;
  }
}

__global__ void zero_acc_kernel() {
  if (threadIdx.x < 4) g_acc[threadIdx.x] = 0.0;
}

// cd = meanF(x) - meanF(x_rec); F = -sum softplus - v.bx
__global__ void finalize_kernel(float *out) {
  double cd = (-g_acc[0] - g_acc[2] + g_acc[1] + g_acc[3]) / (double)BB;
  out[0] = (float)cd;
}

// =============================================================
extern "C" void kernel_launch(void *const *d_in, const int *in_sizes, int n_in,
                              void *d_out, int out_size) {
  (void)in_sizes; (void)n_in; (void)out_size;
  const float *x  = (const float *)d_in[0];
  const float *W  = (const float *)d_in[1];
  const float *bx = (const float *)d_in[2];
  const float *bh = (const float *)d_in[3];

  static int attr_set = 0;
  if (!attr_set) {
    cudaFuncSetAttribute(fused_cd_kernel,
                         cudaFuncAttributeMaxDynamicSharedMemorySize, SMEM_BYTES);
    attr_set = 1;
  }

  zero_acc_kernel<<<1, 32>>>();
  conv_kernel<<<1024, 256>>>(x, bx);
  wsplit_kernel<<<2048, 256>>>(W);

  fused_cd_kernel<<<BB / 64, 256, SMEM_BYTES>>>(bx, bh);

  finalize_kernel<<<1, 1>>>((float *)d_out);
}